// round 16
// baseline (speedup 1.0000x reference)
#include <cuda_runtime.h>
#include <cuda_bf16.h>

#define BATCH 64
#define SEQ   256
#define INP   1024
#define HID   1024
#define NG    4096
#define MTOT  (BATCH*SEQ)
#define NCTA  128

// -------- device scratch ----------
__device__ float g_gin[(size_t)MTOT * NG];   // 256 MB: X @ Wi^T + b_i + b_h
__device__ float g_hbuf[2][BATCH * HID];     // double-buffered hidden state
__device__ float g_c[BATCH * HID];
__device__ unsigned g_bar_count = 0;
__device__ unsigned g_bar_gen   = 0;

// -------- packed f32x2 helpers ----------
__device__ __forceinline__ unsigned long long pack2(float x) {
    unsigned long long r;
    unsigned xi = __float_as_uint(x);
    asm("mov.b64 %0, {%1, %1};" : "=l"(r) : "r"(xi));
    return r;
}
__device__ __forceinline__ void fma2(unsigned long long& d,
                                     unsigned long long a,
                                     unsigned long long b) {
    asm("fma.rn.f32x2 %0, %1, %2, %0;" : "+l"(d) : "l"(a), "l"(b));
}
__device__ __forceinline__ void add2(unsigned long long& d, unsigned long long s) {
    asm("add.rn.f32x2 %0, %0, %1;" : "+l"(d) : "l"(s));
}
__device__ __forceinline__ float2 unpack2(unsigned long long v) {
    unsigned lo, hi;
    asm("mov.b64 {%0, %1}, %2;" : "=r"(lo), "=r"(hi) : "l"(v));
    float2 f;
    f.x = __uint_as_float(lo);
    f.y = __uint_as_float(hi);
    return f;
}

// ---------------------------------------------------------------------------
// Kernel 1: Gin = X @ Wi^T + (b_i + b_h)  [PROVEN 8130 version — unchanged]
// ---------------------------------------------------------------------------
#define GKT 8
__global__ __launch_bounds__(256, 2) void gemm_input(const float* __restrict__ X,
                                                     const float* __restrict__ Wi,
                                                     const float* __restrict__ bi,
                                                     const float* __restrict__ bh) {
    __shared__ float As[2][GKT][132];
    __shared__ float Bs[2][GKT][132];

    const int tid   = threadIdx.x;
    const int mbase = blockIdx.y * 128;
    const int nbase = blockIdx.x * 128;
    const int ty    = tid >> 4;
    const int tx    = tid & 15;
    const int r0    = ty * 8;
    const int lrow  = tid >> 1;
    const int lkq   = (tid & 1) * 4;

    const float* Xrow  = X  + (size_t)(mbase + lrow) * INP + lkq;
    const float* Wirow = Wi + (size_t)(nbase + lrow) * INP + lkq;

    unsigned long long acc[4][8];
#pragma unroll
    for (int i = 0; i < 4; i++)
#pragma unroll
        for (int j = 0; j < 8; j++) acc[i][j] = 0ull;

    {
        float4 va = *(const float4*)(Xrow);
        float4 vb = *(const float4*)(Wirow);
        As[0][lkq + 0][lrow] = va.x; As[0][lkq + 1][lrow] = va.y;
        As[0][lkq + 2][lrow] = va.z; As[0][lkq + 3][lrow] = va.w;
        Bs[0][lkq + 0][lrow] = vb.x; Bs[0][lkq + 1][lrow] = vb.y;
        Bs[0][lkq + 2][lrow] = vb.z; Bs[0][lkq + 3][lrow] = vb.w;
    }
    __syncthreads();

    const int NCHUNK = INP / GKT;
    for (int ck = 0; ck < NCHUNK; ck++) {
        const int cur = ck & 1;
        const int nxt = cur ^ 1;
        const bool pre = (ck + 1) < NCHUNK;
        float4 va, vb;
        if (pre) {
            int kn = (ck + 1) * GKT;
            va = *(const float4*)(Xrow  + kn);
            vb = *(const float4*)(Wirow + kn);
        }
#pragma unroll
        for (int kk = 0; kk < GKT; kk++) {
            ulonglong2 a01 = *(const ulonglong2*)&As[cur][kk][r0];
            ulonglong2 a23 = *(const ulonglong2*)&As[cur][kk][r0 + 4];
            float4 b03 = *(const float4*)&Bs[cur][kk][tx * 8];
            float4 b47 = *(const float4*)&Bs[cur][kk][tx * 8 + 4];
            unsigned long long b2[8];
            b2[0] = pack2(b03.x); b2[1] = pack2(b03.y);
            b2[2] = pack2(b03.z); b2[3] = pack2(b03.w);
            b2[4] = pack2(b47.x); b2[5] = pack2(b47.y);
            b2[6] = pack2(b47.z); b2[7] = pack2(b47.w);
#pragma unroll
            for (int j = 0; j < 8; j++) {
                fma2(acc[0][j], a01.x, b2[j]);
                fma2(acc[1][j], a01.y, b2[j]);
                fma2(acc[2][j], a23.x, b2[j]);
                fma2(acc[3][j], a23.y, b2[j]);
            }
        }
        if (pre) {
            As[nxt][lkq + 0][lrow] = va.x; As[nxt][lkq + 1][lrow] = va.y;
            As[nxt][lkq + 2][lrow] = va.z; As[nxt][lkq + 3][lrow] = va.w;
            Bs[nxt][lkq + 0][lrow] = vb.x; Bs[nxt][lkq + 1][lrow] = vb.y;
            Bs[nxt][lkq + 2][lrow] = vb.z; Bs[nxt][lkq + 3][lrow] = vb.w;
        }
        __syncthreads();
    }

    float bias[8];
#pragma unroll
    for (int j = 0; j < 8; j++) {
        int n = nbase + tx * 8 + j;
        bias[j] = bi[n] + bh[n];
    }
#pragma unroll
    for (int p = 0; p < 4; p++) {
        float lo[8], hi[8];
#pragma unroll
        for (int j = 0; j < 8; j++) {
            float2 v = unpack2(acc[p][j]);
            lo[j] = v.x + bias[j];
            hi[j] = v.y + bias[j];
        }
        size_t mA = (size_t)(mbase + r0 + 2 * p);
        float* dA = &g_gin[mA * NG + nbase + tx * 8];
        float* dB = dA + NG;
        *(float4*)(dA)     = make_float4(lo[0], lo[1], lo[2], lo[3]);
        *(float4*)(dA + 4) = make_float4(lo[4], lo[5], lo[6], lo[7]);
        *(float4*)(dB)     = make_float4(hi[0], hi[1], hi[2], hi[3]);
        *(float4*)(dB + 4) = make_float4(hi[4], hi[5], hi[6], hi[7]);
    }
}

__device__ __forceinline__ float sigmoidf_(float x) {
    return 1.0f / (1.0f + expf(-x));
}

// ---------------------------------------------------------------------------
// Kernel 2: persistent recurrence. 128 CTAs x 256 threads, one barrier/step.
// RKT=64 (17 syncs/step), gin prefetch for t+1 issued between barrier arrival
// and release wait. DEADLOCK FIX vs R14: the last-arriving CTA keeps its OLD
// gen value so its wait predicate is immediately false after the increment.
// ---------------------------------------------------------------------------
#define RKT 64
extern __shared__ float Wsp[];   // 1024 x 32 floats = 128 KB (CTA's Wh slice)

__global__ __launch_bounds__(256, 1) void lstm_recurrent(const float* __restrict__ Wh,
                                                         const float* __restrict__ h0in,
                                                         const float* __restrict__ c0in,
                                                         float* __restrict__ hidden,
                                                         float* __restrict__ hfin,
                                                         float* __restrict__ cfin) {
    __shared__ float Hs[2][RKT][68];    // 34816 B
    __shared__ float Pre[64][36];       // 9216 B
    unsigned long long (*Red)[8] = (unsigned long long(*)[8])&Hs[0][0][0];  // aliases buf 0

    const int tid = threadIdx.x;
    const int c   = blockIdx.x;
    const int u0  = c * 8;

    const int kp = tid >> 7;            // K parity (0/1)
    const int tl = tid & 127;
    const int r0 = (tl >> 3) * 4;       // rows r0..r0+3 (batch)
    const int n0 = (tl & 7) * 4;        // local cols n0..n0+3

    // W slice loader (once)
    const int wn  = tid >> 3;
    const int wkq = (tid & 7) * 4;
    const int wgcol = (wn >> 3) * HID + u0 + (wn & 7);
    const float* Wrow = Wh + (size_t)wgcol * HID;

    // H loader: 4 float4 per thread per chunk (rows lrow4 + j*16, cols lkq4..+3)
    const int lrow4 = tid >> 4;         // 0..15
    const int lkq4  = (tid & 15) * 4;   // 0..60

    const int gcol = (n0 >> 3) * HID + u0 + (n0 & 7);

    const int NCHUNK = HID / RKT;       // 16

    // ---- load this CTA's Wh slice into persistent smem (once) ----
#pragma unroll 4
    for (int kb = 0; kb < 32; kb++) {
        int k = kb * 32 + wkq;
        float4 wv = *(const float4*)(Wrow + k);
        Wsp[(k + 0) * 32 + wn] = wv.x;
        Wsp[(k + 1) * 32 + wn] = wv.y;
        Wsp[(k + 2) * 32 + wn] = wv.z;
        Wsp[(k + 3) * 32 + wn] = wv.w;
    }
    __syncthreads();

    // initial gin prefetch (t = 0)
    float4 g0, g1, g2, g3;
    if (kp == 0) {
        size_t gb = ((size_t)r0 * SEQ + 0) * NG + gcol;
        g0 = *(const float4*)&g_gin[gb];
        g1 = *(const float4*)&g_gin[gb + (size_t)SEQ * NG];
        g2 = *(const float4*)&g_gin[gb + 2 * (size_t)SEQ * NG];
        g3 = *(const float4*)&g_gin[gb + 3 * (size_t)SEQ * NG];
    }

    for (int t = 0; t < SEQ; t++) {
        const float* hsrc = (t == 0) ? h0in : g_hbuf[t & 1];
        float*       hdst = g_hbuf[(t + 1) & 1];

        {   // prologue: load h chunk 0 (4 float4/thread)
#pragma unroll
            for (int j = 0; j < 4; j++) {
                int row = lrow4 + j * 16;
                float4 hv = __ldcg((const float4*)(hsrc + row * HID + lkq4));
                Hs[0][lkq4 + 0][row] = hv.x; Hs[0][lkq4 + 1][row] = hv.y;
                Hs[0][lkq4 + 2][row] = hv.z; Hs[0][lkq4 + 3][row] = hv.w;
            }
        }
        __syncthreads();

        unsigned long long acc[2][4];
#pragma unroll
        for (int p = 0; p < 2; p++)
#pragma unroll
            for (int j = 0; j < 4; j++) acc[p][j] = 0ull;

        for (int ck = 0; ck < NCHUNK; ck++) {
            const int cur = ck & 1;
            const int nxt = cur ^ 1;
            const bool pre = (ck + 1) < NCHUNK;
            float4 ph[4];
            if (pre) {
                int kn = (ck + 1) * RKT;
#pragma unroll
                for (int j = 0; j < 4; j++) {
                    int row = lrow4 + j * 16;
                    ph[j] = __ldcg((const float4*)(hsrc + row * HID + kn + lkq4));
                }
            }
            const float* Wc = Wsp + ck * RKT * 32;
#pragma unroll
            for (int i = 0; i < RKT / 2; i++) {
                const int kk = 2 * i + kp;
                ulonglong2 a = *(const ulonglong2*)&Hs[cur][kk][r0];
                float4 bv = *(const float4*)&Wc[kk * 32 + n0];
                unsigned long long b0 = pack2(bv.x);
                unsigned long long b1 = pack2(bv.y);
                unsigned long long b2 = pack2(bv.z);
                unsigned long long b3 = pack2(bv.w);
                fma2(acc[0][0], a.x, b0); fma2(acc[0][1], a.x, b1);
                fma2(acc[0][2], a.x, b2); fma2(acc[0][3], a.x, b3);
                fma2(acc[1][0], a.y, b0); fma2(acc[1][1], a.y, b1);
                fma2(acc[1][2], a.y, b2); fma2(acc[1][3], a.y, b3);
            }
            if (pre) {
#pragma unroll
                for (int j = 0; j < 4; j++) {
                    int row = lrow4 + j * 16;
                    Hs[nxt][lkq4 + 0][row] = ph[j].x;
                    Hs[nxt][lkq4 + 1][row] = ph[j].y;
                    Hs[nxt][lkq4 + 2][row] = ph[j].z;
                    Hs[nxt][lkq4 + 3][row] = ph[j].w;
                }
            }
            __syncthreads();
        }

        // ---- combine the two K-parity halves (Red aliases Hs buf 0; last
        //      chunk index 15 is odd -> buf 1 was the final read) ----
        if (kp == 1) {
#pragma unroll
            for (int p = 0; p < 2; p++)
#pragma unroll
                for (int j = 0; j < 4; j++)
                    Red[tl][(p * 4 + j + tl) & 7] = acc[p][j];
        }
        __syncthreads();
        if (kp == 0) {
#pragma unroll
            for (int p = 0; p < 2; p++)
#pragma unroll
                for (int j = 0; j < 4; j++)
                    add2(acc[p][j], Red[tl][(p * 4 + j + tl) & 7]);

            float2 u0v = unpack2(acc[0][0]), u1v = unpack2(acc[0][1]);
            float2 u2v = unpack2(acc[0][2]), u3v = unpack2(acc[0][3]);
            float2 v0v = unpack2(acc[1][0]), v1v = unpack2(acc[1][1]);
            float2 v2v = unpack2(acc[1][2]), v3v = unpack2(acc[1][3]);
            *(float4*)&Pre[r0 + 0][n0] =
                make_float4(u0v.x + g0.x, u1v.x + g0.y, u2v.x + g0.z, u3v.x + g0.w);
            *(float4*)&Pre[r0 + 1][n0] =
                make_float4(u0v.y + g1.x, u1v.y + g1.y, u2v.y + g1.z, u3v.y + g1.w);
            *(float4*)&Pre[r0 + 2][n0] =
                make_float4(v0v.x + g2.x, v1v.x + g2.y, v2v.x + g2.z, v3v.x + g2.w);
            *(float4*)&Pre[r0 + 3][n0] =
                make_float4(v0v.y + g3.x, v1v.y + g3.y, v2v.y + g3.z, v3v.y + g3.w);
        }
        __syncthreads();

        // ---- gate math: 512 elements, 2 per thread ----
#pragma unroll
        for (int p = 0; p < 2; p++) {
            int e  = tid + p * 256;
            int b  = e >> 3;
            int ui = e & 7;
            int u  = u0 + ui;
            int ce = b * HID + u;
            float ig = sigmoidf_(Pre[b][ui]);
            float fg = sigmoidf_(Pre[b][8 + ui]);
            float gg = tanhf(Pre[b][16 + ui]);
            float og = sigmoidf_(Pre[b][24 + ui]);
            float cprev = (t == 0) ? c0in[ce] : g_c[ce];
            float cnew = fg * cprev + ig * gg;
            float hnew = og * tanhf(cnew);
            g_c[ce]  = cnew;
            hdst[ce] = hnew;
            hidden[((size_t)b * SEQ + t) * HID + u] = hnew;
            if (t == SEQ - 1) { hfin[ce] = hnew; cfin[ce] = cnew; }
        }

        // ---- grid barrier with gin prefetch in the arrival/release gap ----
        __threadfence();
        __syncthreads();
        unsigned gen = 0;
        if (tid == 0) {
            gen = *(volatile unsigned*)&g_bar_gen;
            unsigned a = atomicAdd(&g_bar_count, 1u);
            if (a == gridDim.x - 1) {
                atomicExch(&g_bar_count, 0u);
                atomicAdd(&g_bar_gen, 1u);
                // keep local gen at the OLD value: g_bar_gen != gen now, so the
                // wait below falls through immediately (R14 deadlock fix).
            }
        }
        // prefetch gin for step t+1 (independent of h; hides DRAM latency)
        if (kp == 0 && t + 1 < SEQ) {
            size_t gb = ((size_t)r0 * SEQ + (t + 1)) * NG + gcol;
            g0 = *(const float4*)&g_gin[gb];
            g1 = *(const float4*)&g_gin[gb + (size_t)SEQ * NG];
            g2 = *(const float4*)&g_gin[gb + 2 * (size_t)SEQ * NG];
            g3 = *(const float4*)&g_gin[gb + 3 * (size_t)SEQ * NG];
        }
        if (tid == 0) {
            while (*(volatile unsigned*)&g_bar_gen == gen) __nanosleep(64);
        }
        __syncthreads();
    }
}

// ---------------------------------------------------------------------------
// kernel_launch
// ---------------------------------------------------------------------------
extern "C" void kernel_launch(void* const* d_in, const int* in_sizes, int n_in,
                              void* d_out, int out_size) {
    const float* X   = (const float*)d_in[0];
    const float* h0  = (const float*)d_in[1];
    const float* c0  = (const float*)d_in[2];
    const float* Wi  = (const float*)d_in[3];
    const float* Wh  = (const float*)d_in[4];
    const float* bi  = (const float*)d_in[5];
    const float* bh  = (const float*)d_in[6];

    float* out    = (float*)d_out;
    float* hidden = out;
    float* hfin   = out + (size_t)BATCH * SEQ * HID;
    float* cfin   = hfin + (size_t)BATCH * HID;

    const int WSMEM = HID * 32 * (int)sizeof(float);   // 128 KB dynamic
    static int attr_done = 0;
    if (!attr_done) {
        cudaFuncSetAttribute(lstm_recurrent,
                             cudaFuncAttributeMaxDynamicSharedMemorySize, WSMEM);
        attr_done = 1;
    }

    gemm_input<<<dim3(NG / 128, MTOT / 128), 256>>>(X, Wi, bi, bh);
    lstm_recurrent<<<NCTA, 256, WSMEM>>>(Wh, h0, c0, hidden, hfin, cfin);
}